// round 4
// baseline (speedup 1.0000x reference)
#include <cuda_runtime.h>
#include <cstdint>

typedef unsigned long long ull;

#define T_STEPS 512
#define BATCH   64
#define DIN     512
#define HID     1024
#define GATES   4096
#define NB      148          // persistent grid size (<= SM count on B300/GB300)
#define CHUNK   256
#define HPAD    260          // 256 + 4 pad -> conflict-free rows, 16B aligned

// ---------------- scratch (static device allocations are allowed) ------------
__device__ float g_G0[(size_t)T_STEPS * BATCH * GATES];   // 512 MB: X@Wih0^T + b
__device__ float g_h0buf[2][BATCH * HID];                 // double-buffered h0
__device__ float g_h1buf[2][BATCH * HID];                 // double-buffered h1
__device__ unsigned g_bar_cnt;
__device__ volatile unsigned g_bar_epoch;

// ---------------- helpers ----------------------------------------------------
__device__ __forceinline__ void ffma2(ull &acc, ull a, ull b) {
    // packed f32x2 FMA: 2x fp32 FLOP per instruction (ptxas never auto-fuses this)
    asm("fma.rn.f32x2 %0, %1, %2, %3;" : "=l"(acc) : "l"(a), "l"(b), "l"(acc));
}
__device__ __forceinline__ float f2sum(ull v) {
    union { ull u; float2 f; } x; x.u = v; return x.f.x + x.f.y;
}
__device__ __forceinline__ float sigmoidf_(float x) {
    return 1.0f / (1.0f + expf(-x));   // precise expf: recurrence-safe
}

__device__ __forceinline__ void grid_sync(int nb, unsigned &my_epoch) {
    __threadfence();
    __syncthreads();
    if (threadIdx.x == 0) {
        my_epoch++;
        if (atomicAdd(&g_bar_cnt, 1u) == (unsigned)nb - 1u) {
            g_bar_cnt = 0u;
            __threadfence();
            g_bar_epoch = my_epoch;
        } else {
            while (g_bar_epoch < my_epoch) { }
            __threadfence();
        }
    }
    __syncthreads();
}

// ---------------- init: zero states + barrier each launch (determinism) ------
__global__ void init_kernel() {
    int tid = blockIdx.x * blockDim.x + threadIdx.x;
    if (tid == 0) { g_bar_cnt = 0u; g_bar_epoch = 0u; }
    for (int i = tid; i < BATCH * HID; i += gridDim.x * blockDim.x) {
        g_h0buf[0][i] = 0.0f; g_h0buf[1][i] = 0.0f;
        g_h1buf[0][i] = 0.0f; g_h1buf[1][i] = 0.0f;
    }
}

// ---------------- precompute G0 = X @ Wih0^T + b_ih0 + b_hh0 -----------------
// M=32768, N=4096, K=512. 64x64 tile, 256 threads, 4x4 per thread,
// f32x2 k-pair accumulation, XOR-swizzled SMEM (float2 granularity).
__global__ void __launch_bounds__(256) gemm_g0(
    const float* __restrict__ X, const float* __restrict__ W,
    const float* __restrict__ bi, const float* __restrict__ bh)
{
    __shared__ ull As[64 * 16];
    __shared__ ull Bs[64 * 16];
    const int tid = threadIdx.x;
    const int tx = tid & 15, ty = tid >> 4;
    const int m0 = blockIdx.y * 64, n0 = blockIdx.x * 64;

    ull acc[4][4];
#pragma unroll
    for (int i = 0; i < 4; i++)
#pragma unroll
        for (int j = 0; j < 4; j++) acc[i][j] = 0ull;

    for (int kb = 0; kb < DIN; kb += 32) {
#pragma unroll
        for (int r = 0; r < 2; r++) {
            int idx = tid + 256 * r;
            int row = idx >> 3, c4 = idx & 7;
            int kk = c4 * 2, s = row & 15;
            ulonglong2 xa = *(const ulonglong2*)&X[(size_t)(m0 + row) * DIN + kb + c4 * 4];
            As[row * 16 + (kk ^ s)]       = xa.x;
            As[row * 16 + ((kk + 1) ^ s)] = xa.y;
            ulonglong2 wb = *(const ulonglong2*)&W[(size_t)(n0 + row) * DIN + kb + c4 * 4];
            Bs[row * 16 + (kk ^ s)]       = wb.x;
            Bs[row * 16 + ((kk + 1) ^ s)] = wb.y;
        }
        __syncthreads();
#pragma unroll
        for (int kk = 0; kk < 16; kk++) {
            ull a[4], b[4];
#pragma unroll
            for (int i = 0; i < 4; i++) {
                int row = ty * 4 + i;
                a[i] = As[row * 16 + (kk ^ (row & 15))];
            }
#pragma unroll
            for (int j = 0; j < 4; j++) {
                int row = tx * 4 + j;
                b[j] = Bs[row * 16 + (kk ^ (row & 15))];
            }
#pragma unroll
            for (int i = 0; i < 4; i++)
#pragma unroll
                for (int j = 0; j < 4; j++) ffma2(acc[i][j], a[i], b[j]);
        }
        __syncthreads();
    }

    float bias[4];
#pragma unroll
    for (int j = 0; j < 4; j++)
        bias[j] = bi[n0 + tx * 4 + j] + bh[n0 + tx * 4 + j];
#pragma unroll
    for (int i = 0; i < 4; i++) {
        float4 v;
        v.x = f2sum(acc[i][0]) + bias[0];
        v.y = f2sum(acc[i][1]) + bias[1];
        v.z = f2sum(acc[i][2]) + bias[2];
        v.w = f2sum(acc[i][3]) + bias[3];
        *(float4*)&g_G0[(size_t)(m0 + ty * 4 + i) * GATES + n0 + tx * 4] = v;
    }
}

// ---------------- persistent recurrent kernel --------------------------------
// 512 threads: tid = b*8 + gate*2 + sub.  Each CTA owns u_count hidden units;
// computes all 4 gates for them (layer0 then layer1), cell update via shfl,
// c-state lives in SMEM across all 512 steps.  Hidden state is DOUBLE-BUFFERED
// in gmem: read parity t&1, write parity (t&1)^1 — no intra-phase read/write
// race across CTAs (the round-3 correctness bug).
__global__ void __launch_bounds__(512) lstm_persistent(
    const float* __restrict__ Whh0, const float* __restrict__ Wih1,
    const float* __restrict__ Whh1, const float* __restrict__ bi1,
    const float* __restrict__ bh1, float* __restrict__ out, int nb)
{
    extern __shared__ float smem[];
    float* h_s  = smem;                    // 64 * HPAD
    float* w_s  = h_s + 64 * HPAD;         // 8 * 4 * HPAD
    float* c0_s = w_s + 8 * 4 * HPAD;      // 8 * 64
    float* c1_s = c0_s + 8 * 64;           // 8 * 64

    const int tid  = threadIdx.x;
    const int sub  = tid & 1;
    const int gate = (tid >> 1) & 3;
    const int b    = tid >> 3;
    const int lane = tid & 31;
    const unsigned baseln = lane & 25u;    // zero gate bits (1,2)
    const int cta = blockIdx.x;

    const int ubase = HID / nb, urem = HID % nb;
    const int u_count = ubase + (cta < urem ? 1 : 0);
    const int u_start = (cta < urem) ? cta * (ubase + 1)
                                     : urem * (ubase + 1) + (cta - urem) * ubase;

    for (int i = tid; i < 8 * 64; i += 512) { c0_s[i] = 0.0f; c1_s[i] = 0.0f; }
    for (int i = tid; i < 8 * 4 * HPAD; i += 512) w_s[i] = 0.0f;  // hygiene: no NaN garbage
    unsigned my_epoch = 0;

    // thread-invariant weight slab base for the hoisted inner loop:
    // lu = 2m+sub  =>  lu*(4*HPAD) = m*(8*HPAD) + sub*(4*HPAD)
    const float* wbase_t = w_s + sub * (4 * HPAD) + gate * HPAD;
    const float* hrow    = h_s + b * HPAD;

    for (int t = 0; t < T_STEPS; t++) {
        const float* h0_prev = g_h0buf[t & 1];
        float*       h0_new  = g_h0buf[(t & 1) ^ 1];
        const float* h1_prev = g_h1buf[t & 1];
        float*       h1_new  = g_h1buf[(t & 1) ^ 1];

        // ================= phase 1: layer 0 (K = 1024) =================
        {
            ull accA[4] = {0ull, 0ull, 0ull, 0ull};
            ull accB[4] = {0ull, 0ull, 0ull, 0ull};
            for (int kc = 0; kc < 4; kc++) {
                const int k0 = kc * CHUNK;
                __syncthreads();
#pragma unroll
                for (int r = 0; r < 8; r++) {            // h0 chunk: 64x256
                    int idx = tid + 512 * r;
                    int row = idx >> 6, c4 = idx & 63;
                    *(float4*)&h_s[row * HPAD + c4 * 4] =
                        *(const float4*)&h0_prev[row * HID + k0 + c4 * 4];
                }
                const int nf4 = u_count * 4 * 64;        // weight rows: 4 gates x units
                for (int idx = tid; idx < nf4; idx += 512) {
                    int row = idx >> 6, c4 = idx & 63;
                    int lu = row >> 2, g = row & 3;
                    *(float4*)&w_s[lu * (4 * HPAD) + g * HPAD + c4 * 4] =
                        *(const float4*)&Whh0[(size_t)(g * HID + u_start + lu) * HID + k0 + c4 * 4];
                }
                __syncthreads();
#pragma unroll 2
                for (int j4 = 0; j4 < 64; j4++) {
                    ulonglong2 hv = *(const ulonglong2*)(hrow + j4 * 4);
#pragma unroll
                    for (int m = 0; m < 4; m++) {
                        ulonglong2 wv = *(const ulonglong2*)(wbase_t + m * (8 * HPAD) + j4 * 4);
                        ffma2(accA[m], hv.x, wv.x);
                        ffma2(accB[m], hv.y, wv.y);
                    }
                }
            }
#pragma unroll
            for (int m = 0; m < 4; m++) {
                int lu = 2 * m + sub;
                bool valid = lu < u_count;
                int u = u_start + lu;
                float s = 0.0f;
                if (valid)
                    s = f2sum(accA[m]) + f2sum(accB[m]) +
                        g_G0[((size_t)t * BATCH + b) * GATES + gate * HID + u];
                float gi = __shfl_sync(0xffffffffu, s, baseln);
                float gf = __shfl_sync(0xffffffffu, s, baseln + 2);
                float gg = __shfl_sync(0xffffffffu, s, baseln + 4);
                float go = __shfl_sync(0xffffffffu, s, baseln + 6);
                if (gate == 0 && valid) {
                    float i_ = sigmoidf_(gi), f_ = sigmoidf_(gf);
                    float g_ = tanhf(gg),     o_ = sigmoidf_(go);
                    float c = f_ * c0_s[lu * 64 + b] + i_ * g_;
                    c0_s[lu * 64 + b] = c;
                    h0_new[b * HID + u] = o_ * tanhf(c);
                }
            }
        }
        grid_sync(nb, my_epoch);

        // ================= phase 2: layer 1 (K = 2048) =================
        {
            ull accA[4] = {0ull, 0ull, 0ull, 0ull};
            ull accB[4] = {0ull, 0ull, 0ull, 0ull};
            for (int kc = 0; kc < 8; kc++) {
                const float* hsrc = (kc < 4) ? h0_new : h1_prev;  // h0_new is stable post-sync
                const float* Wsrc = (kc < 4) ? Wih1 : Whh1;
                const int k0 = (kc & 3) * CHUNK;
                __syncthreads();
#pragma unroll
                for (int r = 0; r < 8; r++) {
                    int idx = tid + 512 * r;
                    int row = idx >> 6, c4 = idx & 63;
                    *(float4*)&h_s[row * HPAD + c4 * 4] =
                        *(const float4*)&hsrc[row * HID + k0 + c4 * 4];
                }
                const int nf4 = u_count * 4 * 64;
                for (int idx = tid; idx < nf4; idx += 512) {
                    int row = idx >> 6, c4 = idx & 63;
                    int lu = row >> 2, g = row & 3;
                    *(float4*)&w_s[lu * (4 * HPAD) + g * HPAD + c4 * 4] =
                        *(const float4*)&Wsrc[(size_t)(g * HID + u_start + lu) * HID + k0 + c4 * 4];
                }
                __syncthreads();
#pragma unroll 2
                for (int j4 = 0; j4 < 64; j4++) {
                    ulonglong2 hv = *(const ulonglong2*)(hrow + j4 * 4);
#pragma unroll
                    for (int m = 0; m < 4; m++) {
                        ulonglong2 wv = *(const ulonglong2*)(wbase_t + m * (8 * HPAD) + j4 * 4);
                        ffma2(accA[m], hv.x, wv.x);
                        ffma2(accB[m], hv.y, wv.y);
                    }
                }
            }
#pragma unroll
            for (int m = 0; m < 4; m++) {
                int lu = 2 * m + sub;
                bool valid = lu < u_count;
                int u = u_start + lu;
                float s = 0.0f;
                if (valid)
                    s = f2sum(accA[m]) + f2sum(accB[m]) +
                        bi1[gate * HID + u] + bh1[gate * HID + u];
                float gi = __shfl_sync(0xffffffffu, s, baseln);
                float gf = __shfl_sync(0xffffffffu, s, baseln + 2);
                float gg = __shfl_sync(0xffffffffu, s, baseln + 4);
                float go = __shfl_sync(0xffffffffu, s, baseln + 6);
                if (gate == 0 && valid) {
                    float i_ = sigmoidf_(gi), f_ = sigmoidf_(gf);
                    float g_ = tanhf(gg),     o_ = sigmoidf_(go);
                    float c = f_ * c1_s[lu * 64 + b] + i_ * g_;
                    c1_s[lu * 64 + b] = c;
                    float h = o_ * tanhf(c);
                    h1_new[b * HID + u] = h;
                    out[((size_t)t * BATCH + b) * HID + u] = h;
                }
            }
        }
        grid_sync(nb, my_epoch);
    }

    // ---- final states: outputs | h0 | c0 | h1 | c1 ----
    // T_STEPS even: last write went to buffer ((T-1)&1)^1 == 0.
    const float* h0_fin = g_h0buf[0];
    const float* h1_fin = g_h1buf[0];
    float* so = out + (size_t)T_STEPS * BATCH * HID;
    for (int idx = tid; idx < u_count * 64; idx += 512) {
        int lu = idx >> 6, bb = idx & 63;
        int u = u_start + lu;
        so[bb * HID + u]               = h0_fin[bb * HID + u];
        so[65536 + bb * HID + u]       = c0_s[lu * 64 + bb];
        so[131072 + bb * HID + u]      = h1_fin[bb * HID + u];
        so[196608 + bb * HID + u]      = c1_s[lu * 64 + bb];
    }
}

// ---------------- launch ------------------------------------------------------
extern "C" void kernel_launch(void* const* d_in, const int* in_sizes, int n_in,
                              void* d_out, int out_size) {
    const float* X     = (const float*)d_in[0];
    const float* Wih0  = (const float*)d_in[1];
    const float* Whh0  = (const float*)d_in[2];
    const float* bih0  = (const float*)d_in[3];
    const float* bhh0  = (const float*)d_in[4];
    const float* Wih1  = (const float*)d_in[5];
    const float* Whh1  = (const float*)d_in[6];
    const float* bih1  = (const float*)d_in[7];
    const float* bhh1  = (const float*)d_in[8];
    float* out = (float*)d_out;

    init_kernel<<<64, 256>>>();

    dim3 ggrid(GATES / 64, (T_STEPS * BATCH) / 64);   // 64 x 512 blocks
    gemm_g0<<<ggrid, 256>>>(X, Wih0, bih0, bhh0);

    const int smem_bytes = (64 * HPAD + 8 * 4 * HPAD + 8 * 64 + 8 * 64) * (int)sizeof(float);
    cudaFuncSetAttribute(lstm_persistent,
                         cudaFuncAttributeMaxDynamicSharedMemorySize, smem_bytes);
    lstm_persistent<<<NB, 512, smem_bytes>>>(Whh0, Wih1, Whh1, bih1, bhh1, out, NB);
}

// round 6
// speedup vs baseline: 3.0525x; 3.0525x over previous
#include <cuda_runtime.h>
#include <cstdint>

typedef unsigned long long ull;

#define T_STEPS 512
#define BATCH   64
#define DIN     512
#define HID     1024
#define GATES   4096
#define NB      128          // 128 CTAs * 8 units = 1024, perfectly uniform
#define NTHREADS 512
#define UPC     8            // units per CTA
#define NCOLS   32           // 8 units * 4 gates (unit-major: col = u*4 + gate)
#define CHUNK   256
#define SROW    260          // smem row stride (floats): 256 + 4 pad, 16B aligned

// ---------------- scratch -----------------------------------------------------
__device__ float g_G0[(size_t)T_STEPS * BATCH * GATES];   // [t*64+b][4096]
__device__ float g_h0buf[2][BATCH * HID];
__device__ float g_h1buf[2][BATCH * HID];
__device__ unsigned g_bar_cnt;
__device__ volatile unsigned g_bar_epoch;
__device__ unsigned g_done_cnt;

// ---------------- helpers -----------------------------------------------------
__device__ __forceinline__ void ffma2(ull &acc, ull a, ull b) {
    asm("fma.rn.f32x2 %0, %1, %2, %0;" : "+l"(acc) : "l"(a), "l"(b));
}
__device__ __forceinline__ void add2(ull &a, ull b) {
    asm("add.rn.f32x2 %0, %0, %1;" : "+l"(a) : "l"(b));
}
__device__ __forceinline__ float f2sum(ull v) {
    union { ull u; float2 f; } x; x.u = v; return x.f.x + x.f.y;
}
__device__ __forceinline__ float sigmoidf_(float x) {
    return 1.0f / (1.0f + expf(-x));
}

__device__ __forceinline__ void grid_sync(unsigned &my_epoch) {
    __threadfence();
    __syncthreads();
    if (threadIdx.x == 0) {
        my_epoch++;
        if (atomicAdd(&g_bar_cnt, 1u) == (unsigned)NB - 1u) {
            g_bar_cnt = 0u;
            __threadfence();
            g_bar_epoch = my_epoch;
        } else {
            while (g_bar_epoch < my_epoch) { }
            __threadfence();
        }
    }
    __syncthreads();
}

// ---------------- precompute G0 = X @ Wih0^T + b_ih0 + b_hh0 ------------------
// (unchanged from the passing round-4 kernel)
__global__ void __launch_bounds__(256) gemm_g0(
    const float* __restrict__ X, const float* __restrict__ W,
    const float* __restrict__ bi, const float* __restrict__ bh)
{
    __shared__ ull As[64 * 16];
    __shared__ ull Bs[64 * 16];
    const int tid = threadIdx.x;
    const int tx = tid & 15, ty = tid >> 4;
    const int m0 = blockIdx.y * 64, n0 = blockIdx.x * 64;

    ull acc[4][4];
#pragma unroll
    for (int i = 0; i < 4; i++)
#pragma unroll
        for (int j = 0; j < 4; j++) acc[i][j] = 0ull;

    for (int kb = 0; kb < DIN; kb += 32) {
#pragma unroll
        for (int r = 0; r < 2; r++) {
            int idx = tid + 256 * r;
            int row = idx >> 3, c4 = idx & 7;
            int kk = c4 * 2, s = row & 15;
            ulonglong2 xa = *(const ulonglong2*)&X[(size_t)(m0 + row) * DIN + kb + c4 * 4];
            As[row * 16 + (kk ^ s)]       = xa.x;
            As[row * 16 + ((kk + 1) ^ s)] = xa.y;
            ulonglong2 wb = *(const ulonglong2*)&W[(size_t)(n0 + row) * DIN + kb + c4 * 4];
            Bs[row * 16 + (kk ^ s)]       = wb.x;
            Bs[row * 16 + ((kk + 1) ^ s)] = wb.y;
        }
        __syncthreads();
#pragma unroll
        for (int kk = 0; kk < 16; kk++) {
            ull a[4], b[4];
#pragma unroll
            for (int i = 0; i < 4; i++) {
                int row = ty * 4 + i;
                a[i] = As[row * 16 + (kk ^ (row & 15))];
            }
#pragma unroll
            for (int j = 0; j < 4; j++) {
                int row = tx * 4 + j;
                b[j] = Bs[row * 16 + (kk ^ (row & 15))];
            }
#pragma unroll
            for (int i = 0; i < 4; i++)
#pragma unroll
                for (int j = 0; j < 4; j++) ffma2(acc[i][j], a[i], b[j]);
        }
        __syncthreads();
    }

    float bias[4];
#pragma unroll
    for (int j = 0; j < 4; j++)
        bias[j] = bi[n0 + tx * 4 + j] + bh[n0 + tx * 4 + j];
#pragma unroll
    for (int i = 0; i < 4; i++) {
        float4 v;
        v.x = f2sum(acc[i][0]) + bias[0];
        v.y = f2sum(acc[i][1]) + bias[1];
        v.z = f2sum(acc[i][2]) + bias[2];
        v.w = f2sum(acc[i][3]) + bias[3];
        *(float4*)&g_G0[(size_t)(m0 + ty * 4 + i) * GATES + n0 + tx * 4] = v;
    }
}

// ---------------- chunk loaders (XOR-swizzled SMEM) ---------------------------
// h chunk: 64 rows (batch) x 256 k  -> h_s[row*SROW + 4*(c4 ^ ((row>>2)&3))]
__device__ __forceinline__ void load_h_chunk(float* h_s, const float* __restrict__ src,
                                             int k0, int tid) {
#pragma unroll
    for (int r = 0; r < 8; r++) {
        int idx = tid + NTHREADS * r;
        int row = idx >> 6, c4 = idx & 63;
        int swz = c4 ^ ((row >> 2) & 3);
        *(float4*)&h_s[row * SROW + swz * 4] =
            *(const float4*)&src[row * HID + k0 + c4 * 4];
    }
}
// w chunk: 32 rows (col = u*4+g) x 256 k -> w_s[row*SROW + 4*(c4 ^ (u&7))]
__device__ __forceinline__ void load_w_chunk(float* w_s, const float* __restrict__ W,
                                             int u_start, int k0, int tid) {
#pragma unroll
    for (int r = 0; r < 4; r++) {
        int idx = tid + NTHREADS * r;
        int row = idx >> 6, c4 = idx & 63;
        int uu = row >> 2, g = row & 3;
        int swz = c4 ^ (uu & 7);
        *(float4*)&w_s[row * SROW + swz * 4] =
            *(const float4*)&W[(size_t)(g * HID + u_start + uu) * HID + k0 + c4 * 4];
    }
}

// 4x4 register-tile compute over this kgroup's 64-k slice of the chunk
__device__ __forceinline__ void chunk_compute(const float* h_s, const float* w_s,
                                              int kg, int ti, int tj, ull acc[4][4]) {
#pragma unroll 4
    for (int kk = 0; kk < 16; kk++) {
        int k4 = (kg << 4) + kk;
        int hsw = 4 * (k4 ^ (ti & 3));
        int wsw = 4 * (k4 ^ tj);
        ull hx[4], hy[4], wx[4], wy[4];
#pragma unroll
        for (int bb = 0; bb < 4; bb++) {
            ulonglong2 v = *(const ulonglong2*)&h_s[(4 * ti + bb) * SROW + hsw];
            hx[bb] = v.x; hy[bb] = v.y;
        }
#pragma unroll
        for (int cc = 0; cc < 4; cc++) {
            ulonglong2 v = *(const ulonglong2*)&w_s[(4 * tj + cc) * SROW + wsw];
            wx[cc] = v.x; wy[cc] = v.y;
        }
#pragma unroll
        for (int bb = 0; bb < 4; bb++)
#pragma unroll
            for (int cc = 0; cc < 4; cc++) ffma2(acc[bb][cc], hx[bb], wx[cc]);
#pragma unroll
        for (int bb = 0; bb < 4; bb++)
#pragma unroll
            for (int cc = 0; cc < 4; cc++) ffma2(acc[bb][cc], hy[bb], wy[cc]);
    }
}

// reduce kgroups 1-3 into kgroup 0's acc via smem (aliases h_s; conflict-free
// [slot][t128] interleave). Returns with valid totals only in kg==0 threads.
__device__ __forceinline__ void kgroup_reduce(float* h_s, int kg, int t128, ull acc[4][4]) {
    __syncthreads();                       // all compute on h_s/w_s done
    ull* red = (ull*)h_s;
    if (kg > 0) {
#pragma unroll
        for (int n = 0; n < 16; n++)
            red[((size_t)(kg - 1) * 16 + n) * 128 + t128] = acc[n >> 2][n & 3];
    }
    __syncthreads();
    if (kg == 0) {
#pragma unroll
        for (int p = 0; p < 3; p++)
#pragma unroll
            for (int n = 0; n < 16; n++)
                add2(acc[n >> 2][n & 3], red[((size_t)p * 16 + n) * 128 + t128]);
    }
}

// ---------------- persistent recurrent kernel ---------------------------------
__global__ void __launch_bounds__(NTHREADS) lstm_persistent(
    const float* __restrict__ Whh0, const float* __restrict__ Wih1,
    const float* __restrict__ Whh1, const float* __restrict__ bi1,
    const float* __restrict__ bh1, float* __restrict__ out)
{
    extern __shared__ float smem[];
    float* h_s  = smem;                    // 64 * SROW
    float* w_s  = h_s + 64 * SROW;         // 32 * SROW
    float* c0_s = w_s + 32 * SROW;         // 512   [unit][batch]
    float* c1_s = c0_s + 512;              // 512

    const int tid  = threadIdx.x;
    const int kg   = tid >> 7;             // 0..3 k-group
    const int t128 = tid & 127;
    const int ti   = t128 >> 3;            // 0..15 batch tile (4 batches)
    const int tj   = t128 & 7;             // 0..7 unit (4 gates = 4 cols)
    const int cta  = blockIdx.x;
    const int u_start = cta * UPC;
    const int u = u_start + tj;

    float bias1[4];
    if (kg == 0) {
#pragma unroll
        for (int g = 0; g < 4; g++)
            bias1[g] = bi1[g * HID + u] + bh1[g * HID + u];
    }

    // zero states (each CTA owns 512 floats of each buffer) + cell state
    {
        int i0 = cta * NTHREADS + tid;
        g_h0buf[0][i0] = 0.0f; g_h0buf[1][i0] = 0.0f;
        g_h1buf[0][i0] = 0.0f; g_h1buf[1][i0] = 0.0f;
    }
    c0_s[tid] = 0.0f; c1_s[tid] = 0.0f;
    unsigned my_epoch = 0;
    grid_sync(my_epoch);                   // all zeros visible chip-wide

    for (int t = 0; t < T_STEPS; t++) {
        const float* h0_prev = g_h0buf[t & 1];
        float*       h0_new  = g_h0buf[(t & 1) ^ 1];
        const float* h1_prev = g_h1buf[t & 1];
        float*       h1_new  = g_h1buf[(t & 1) ^ 1];

        // ================= phase 1: layer 0 (K = 1024) =================
        {
            ull acc[4][4];
#pragma unroll
            for (int a = 0; a < 4; a++)
#pragma unroll
                for (int b2 = 0; b2 < 4; b2++) acc[a][b2] = 0ull;
            for (int kc = 0; kc < 4; kc++) {
                const int k0 = kc * CHUNK;
                __syncthreads();
                load_h_chunk(h_s, h0_prev, k0, tid);
                load_w_chunk(w_s, Whh0, u_start, k0, tid);
                __syncthreads();
                chunk_compute(h_s, w_s, kg, ti, tj, acc);
            }
            kgroup_reduce(h_s, kg, t128, acc);
            if (kg == 0) {
                float4 cv = *(float4*)&c0_s[tj * 64 + 4 * ti];
                float cold[4] = {cv.x, cv.y, cv.z, cv.w};
                float cn[4];
                const float* g0base = &g_G0[(size_t)t * BATCH * GATES + u];
#pragma unroll
                for (int bb = 0; bb < 4; bb++) {
                    int b = 4 * ti + bb;
                    const float* gp = g0base + (size_t)b * GATES;
                    float gi = f2sum(acc[bb][0]) + gp[0];
                    float gf = f2sum(acc[bb][1]) + gp[HID];
                    float gg = f2sum(acc[bb][2]) + gp[2 * HID];
                    float go = f2sum(acc[bb][3]) + gp[3 * HID];
                    float c = sigmoidf_(gf) * cold[bb] + sigmoidf_(gi) * tanhf(gg);
                    cn[bb] = c;
                    h0_new[b * HID + u] = sigmoidf_(go) * tanhf(c);
                }
                *(float4*)&c0_s[tj * 64 + 4 * ti] = make_float4(cn[0], cn[1], cn[2], cn[3]);
            }
        }
        grid_sync(my_epoch);

        // ================= phase 2: layer 1 (K = 2048) =================
        {
            ull acc[4][4];
#pragma unroll
            for (int a = 0; a < 4; a++)
#pragma unroll
                for (int b2 = 0; b2 < 4; b2++) acc[a][b2] = 0ull;
            for (int kc = 0; kc < 8; kc++) {
                const float* hsrc = (kc < 4) ? h0_new : h1_prev;
                const float* Wsrc = (kc < 4) ? Wih1 : Whh1;
                const int k0 = (kc & 3) * CHUNK;
                __syncthreads();
                load_h_chunk(h_s, hsrc, k0, tid);
                load_w_chunk(w_s, Wsrc, u_start, k0, tid);
                __syncthreads();
                chunk_compute(h_s, w_s, kg, ti, tj, acc);
            }
            kgroup_reduce(h_s, kg, t128, acc);
            if (kg == 0) {
                float4 cv = *(float4*)&c1_s[tj * 64 + 4 * ti];
                float cold[4] = {cv.x, cv.y, cv.z, cv.w};
                float cn[4];
                float* orow = out + (size_t)t * BATCH * HID + u;
#pragma unroll
                for (int bb = 0; bb < 4; bb++) {
                    int b = 4 * ti + bb;
                    float gi = f2sum(acc[bb][0]) + bias1[0];
                    float gf = f2sum(acc[bb][1]) + bias1[1];
                    float gg = f2sum(acc[bb][2]) + bias1[2];
                    float go = f2sum(acc[bb][3]) + bias1[3];
                    float c = sigmoidf_(gf) * cold[bb] + sigmoidf_(gi) * tanhf(gg);
                    cn[bb] = c;
                    float h = sigmoidf_(go) * tanhf(c);
                    h1_new[b * HID + u] = h;
                    orow[(size_t)b * HID] = h;
                }
                *(float4*)&c1_s[tj * 64 + 4 * ti] = make_float4(cn[0], cn[1], cn[2], cn[3]);
            }
        }
        grid_sync(my_epoch);
    }

    // ---- final states: outputs | h0 | c0 | h1 | c1 (T even -> buffer 0) ----
    const float* h0_fin = g_h0buf[0];
    const float* h1_fin = g_h1buf[0];
    float* so = out + (size_t)T_STEPS * BATCH * HID;
    {
        int lu = tid >> 6, bb = tid & 63;
        int uu = u_start + lu;
        so[bb * HID + uu]          = h0_fin[bb * HID + uu];
        so[65536 + bb * HID + uu]  = c0_s[lu * 64 + bb];
        so[131072 + bb * HID + uu] = h1_fin[bb * HID + uu];
        so[196608 + bb * HID + uu] = c1_s[lu * 64 + bb];
    }

    // ---- reset barrier vars so graph replays are deterministic ----
    __threadfence();
    __syncthreads();
    if (tid == 0) {
        if (atomicAdd(&g_done_cnt, 1u) == (unsigned)NB - 1u) {
            g_done_cnt = 0u;
            g_bar_cnt  = 0u;
            __threadfence();
            g_bar_epoch = 0u;
        }
    }
}

// ---------------- launch ------------------------------------------------------
extern "C" void kernel_launch(void* const* d_in, const int* in_sizes, int n_in,
                              void* d_out, int out_size) {
    const float* X     = (const float*)d_in[0];
    const float* Wih0  = (const float*)d_in[1];
    const float* Whh0  = (const float*)d_in[2];
    const float* bih0  = (const float*)d_in[3];
    const float* bhh0  = (const float*)d_in[4];
    const float* Wih1  = (const float*)d_in[5];
    const float* Whh1  = (const float*)d_in[6];
    const float* bih1  = (const float*)d_in[7];
    const float* bhh1  = (const float*)d_in[8];
    float* out = (float*)d_out;

    dim3 ggrid(GATES / 64, (T_STEPS * BATCH) / 64);   // 64 x 512 blocks
    gemm_g0<<<ggrid, 256>>>(X, Wih0, bih0, bhh0);

    const int smem_bytes = (64 * SROW + 32 * SROW + 512 + 512) * (int)sizeof(float);
    cudaFuncSetAttribute(lstm_persistent,
                         cudaFuncAttributeMaxDynamicSharedMemorySize, smem_bytes);
    lstm_persistent<<<NB, NTHREADS, smem_bytes>>>(Whh0, Wih1, Whh1, bih1, bhh1, out);
}

// round 8
// speedup vs baseline: 3.6316x; 1.1897x over previous
#include <cuda_runtime.h>
#include <cuda_bf16.h>
#include <cstdint>

typedef unsigned long long ull;
typedef unsigned int uint;

#define T_STEPS 512
#define BATCH   64
#define DIN     512
#define HID     1024
#define GATES   4096
#define NB      128          // persistent grid: 128 CTAs x 8 units = 1024
#define NTH     512          // 16 warps: mi = w&3 (16-row), ni = w>>2 (8-col)
#define UPC     8

// ---------------- scratch -----------------------------------------------------
__device__ float g_G0[(size_t)T_STEPS * BATCH * GATES];       // X@Wih0^T + biases
// weights in per-lane B-fragment order: [cta][mat 3][ni 4][kstep 64][lane 32]
// each entry uint4 = {b0h, b1h, b0l, b1l}
__device__ uint4 g_wf[(size_t)NB * 3 * 4 * 64 * 32];
// hidden states in A-fragment order: [parity][hi/lo][((mt*64+ks)*32+lane)*4+reg]
__device__ uint g_h0f[2][2][32768];
__device__ uint g_h1f[2][2][32768];
__device__ unsigned g_bar_cnt;
__device__ volatile unsigned g_bar_epoch;
__device__ unsigned g_done_cnt;

// ---------------- helpers -----------------------------------------------------
__device__ __forceinline__ void ffma2(ull &acc, ull a, ull b) {
    asm("fma.rn.f32x2 %0, %1, %2, %0;" : "+l"(acc) : "l"(a), "l"(b));
}
__device__ __forceinline__ float f2sum(ull v) {
    union { ull u; float2 f; } x; x.u = v; return x.f.x + x.f.y;
}
__device__ __forceinline__ float sigmoidf_(float x) { return 1.0f / (1.0f + expf(-x)); }

__device__ __forceinline__ void mma16816(float d[4], uint a0, uint a1, uint a2, uint a3,
                                         uint b0, uint b1) {
    asm volatile("mma.sync.aligned.m16n8k16.row.col.f32.bf16.bf16.f32 "
        "{%0,%1,%2,%3}, {%4,%5,%6,%7}, {%8,%9}, {%0,%1,%2,%3};"
        : "+f"(d[0]), "+f"(d[1]), "+f"(d[2]), "+f"(d[3])
        : "r"(a0), "r"(a1), "r"(a2), "r"(a3), "r"(b0), "r"(b1));
}

__device__ __forceinline__ void grid_sync(unsigned &my_epoch) {
    __threadfence();
    __syncthreads();
    if (threadIdx.x == 0) {
        my_epoch++;
        if (atomicAdd(&g_bar_cnt, 1u) == (unsigned)NB - 1u) {
            g_bar_cnt = 0u;
            __threadfence();
            g_bar_epoch = my_epoch;
        } else {
            while (g_bar_epoch < my_epoch) { }
            __threadfence();
        }
    }
    __syncthreads();
}

__device__ __forceinline__ uint pack_bf2(__nv_bfloat16 lo16, __nv_bfloat16 hi16) {
    return (uint)__bfloat16_as_ushort(lo16) | ((uint)__bfloat16_as_ushort(hi16) << 16);
}

// ---------------- prep: weights -> B-fragment order, bf16 hi/lo ---------------
// idx = (((cta*3+mat)*4+ni)*64 + ks)*32 + lane
__global__ void __launch_bounds__(256) prep_w(
    const float* __restrict__ Whh0, const float* __restrict__ Wih1,
    const float* __restrict__ Whh1)
{
    uint idx = blockIdx.x * 256u + threadIdx.x;
    uint lane = idx & 31u;
    uint ks   = (idx >> 5) & 63u;
    uint ni   = (idx >> 11) & 3u;
    uint cm   = idx >> 13;
    uint mat  = cm % 3u, cta = cm / 3u;

    const float* W = (mat == 0) ? Whh0 : (mat == 1) ? Wih1 : Whh1;
    uint n  = ni * 8u + (lane >> 2);       // col within CTA's 32: n = lu*4 + g
    uint lu = n >> 2, g = n & 3u;
    const float* row = W + (size_t)(g * HID + cta * UPC + lu) * HID;
    uint k0 = ks * 16u + (lane & 3u) * 2u;

    float f0 = row[k0],     f1 = row[k0 + 1];
    float f2 = row[k0 + 8], f3 = row[k0 + 9];
    __nv_bfloat16 h0 = __float2bfloat16(f0), h1 = __float2bfloat16(f1);
    __nv_bfloat16 h2 = __float2bfloat16(f2), h3 = __float2bfloat16(f3);
    uint4 v;
    v.x = pack_bf2(h0, h1);
    v.y = pack_bf2(h2, h3);
    v.z = pack_bf2(__float2bfloat16(f0 - __bfloat162float(h0)),
                   __float2bfloat16(f1 - __bfloat162float(h1)));
    v.w = pack_bf2(__float2bfloat16(f2 - __bfloat162float(h2)),
                   __float2bfloat16(f3 - __bfloat162float(h3)));
    g_wf[idx] = v;
}

// ---------------- precompute G0 = X @ Wih0^T + b (unchanged, proven) ----------
__global__ void __launch_bounds__(256) gemm_g0(
    const float* __restrict__ X, const float* __restrict__ W,
    const float* __restrict__ bi, const float* __restrict__ bh)
{
    __shared__ ull As[64 * 16];
    __shared__ ull Bs[64 * 16];
    const int tid = threadIdx.x;
    const int tx = tid & 15, ty = tid >> 4;
    const int m0 = blockIdx.y * 64, n0 = blockIdx.x * 64;

    ull acc[4][4];
#pragma unroll
    for (int i = 0; i < 4; i++)
#pragma unroll
        for (int j = 0; j < 4; j++) acc[i][j] = 0ull;

    for (int kb = 0; kb < DIN; kb += 32) {
#pragma unroll
        for (int r = 0; r < 2; r++) {
            int idx = tid + 256 * r;
            int row = idx >> 3, c4 = idx & 7;
            int kk = c4 * 2, s = row & 15;
            ulonglong2 xa = *(const ulonglong2*)&X[(size_t)(m0 + row) * DIN + kb + c4 * 4];
            As[row * 16 + (kk ^ s)]       = xa.x;
            As[row * 16 + ((kk + 1) ^ s)] = xa.y;
            ulonglong2 wb = *(const ulonglong2*)&W[(size_t)(n0 + row) * DIN + kb + c4 * 4];
            Bs[row * 16 + (kk ^ s)]       = wb.x;
            Bs[row * 16 + ((kk + 1) ^ s)] = wb.y;
        }
        __syncthreads();
#pragma unroll
        for (int kk = 0; kk < 16; kk++) {
            ull a[4], b[4];
#pragma unroll
            for (int i = 0; i < 4; i++) { int row = ty * 4 + i; a[i] = As[row * 16 + (kk ^ (row & 15))]; }
#pragma unroll
            for (int j = 0; j < 4; j++) { int row = tx * 4 + j; b[j] = Bs[row * 16 + (kk ^ (row & 15))]; }
#pragma unroll
            for (int i = 0; i < 4; i++)
#pragma unroll
                for (int j = 0; j < 4; j++) ffma2(acc[i][j], a[i], b[j]);
        }
        __syncthreads();
    }

    float bias[4];
#pragma unroll
    for (int j = 0; j < 4; j++) bias[j] = bi[n0 + tx * 4 + j] + bh[n0 + tx * 4 + j];
#pragma unroll
    for (int i = 0; i < 4; i++) {
        float4 v;
        v.x = f2sum(acc[i][0]) + bias[0];
        v.y = f2sum(acc[i][1]) + bias[1];
        v.z = f2sum(acc[i][2]) + bias[2];
        v.w = f2sum(acc[i][3]) + bias[3];
        *(float4*)&g_G0[(size_t)(m0 + ty * 4 + i) * GATES + n0 + tx * 4] = v;
    }
}

// ---------------- k-loop: A/B fragments from gmem, 3-term split-bf16 ----------
__device__ __forceinline__ void run_phase(
    const uint* __restrict__ ah_base, const uint* __restrict__ al_base,
    const uint4* __restrict__ bf_base, int mi, int lane, float d[4])
{
    const uint4* ah = (const uint4*)ah_base + (size_t)mi * 64 * 32 + lane;
    const uint4* al = (const uint4*)al_base + (size_t)mi * 64 * 32 + lane;
    const uint4* bf = bf_base + lane;
#pragma unroll 2
    for (int ks = 0; ks < 64; ks++) {
        uint4 a_h = ah[ks * 32];
        uint4 a_l = al[ks * 32];
        uint4 bv  = bf[ks * 32];
        mma16816(d, a_h.x, a_h.y, a_h.z, a_h.w, bv.x, bv.y);   // hi*hi
        mma16816(d, a_l.x, a_l.y, a_l.z, a_l.w, bv.x, bv.y);   // lo*hi
        mma16816(d, a_h.x, a_h.y, a_h.z, a_h.w, bv.z, bv.w);   // hi*lo
    }
}

// epilogue helper: split h to bf16 hi/lo and write A-fragment slots
__device__ __forceinline__ void store_hfrag(uint* dst_hi, uint* dst_lo,
                                            const float hf[8], int b, int cta) {
    int kstep = cta >> 1, khalf = cta & 1;
    int row = b & 15, mt = b >> 4;
    int regb = ((row >= 8) ? 1 : 0) + (khalf ? 2 : 0);
    int base = (mt * 64 + kstep) * 32 + (row & 7) * 4;
#pragma unroll
    for (int s = 0; s < 4; s++) {
        float x = hf[2 * s], y = hf[2 * s + 1];
        __nv_bfloat16 xh = __float2bfloat16(x), yh = __float2bfloat16(y);
        int idx = (base + s) * 4 + regb;
        dst_hi[idx] = pack_bf2(xh, yh);
        dst_lo[idx] = pack_bf2(__float2bfloat16(x - __bfloat162float(xh)),
                               __float2bfloat16(y - __bfloat162float(yh)));
    }
}

// ---------------- persistent recurrent kernel ---------------------------------
__global__ void __launch_bounds__(NTH) lstm_persistent(
    const float* __restrict__ bi1, const float* __restrict__ bh1,
    float* __restrict__ out)
{
    __shared__ float ds[64 * 33];          // D routing tile, pad 33 -> conflict-free

    const int tid  = threadIdx.x;
    const int lane = tid & 31;
    const int warp = tid >> 5;
    const int mi   = warp & 3;             // 16-row tile
    const int ni   = warp >> 2;            // 8-col tile
    const int cta  = blockIdx.x;
    const int u_start = cta * UPC;

    // zero parity-0 h fragments (first 65536 u32 of each array = parity 0 hi+lo)
    {
        int i0 = cta * NTH + tid;          // 0..65535
        ((uint*)g_h0f)[i0] = 0u;
        ((uint*)g_h1f)[i0] = 0u;
    }
    float c0r[8], c1r[8];
#pragma unroll
    for (int u = 0; u < 8; u++) { c0r[u] = 0.f; c1r[u] = 0.f; }
    float b1r[32];
    if (tid < 64) {
#pragma unroll
        for (int g = 0; g < 4; g++)
#pragma unroll
            for (int u = 0; u < 8; u++)
                b1r[g * 8 + u] = bi1[g * HID + u_start + u] + bh1[g * HID + u_start + u];
    }

    unsigned my_epoch = 0;
    grid_sync(my_epoch);

    const uint4* wf0 = g_wf + ((size_t)(cta * 3 + 0) * 4 + ni) * 2048;
    const uint4* wf1 = g_wf + ((size_t)(cta * 3 + 1) * 4 + ni) * 2048;
    const uint4* wf2 = g_wf + ((size_t)(cta * 3 + 2) * 4 + ni) * 2048;

    const int r0  = 16 * mi + (lane >> 2);
    const int cc0 = 8 * ni + (lane & 3) * 2;

    for (int t = 0; t < T_STEPS; t++) {
        const int par = t & 1, nxt = par ^ 1;

        // ===== phase 1: layer 0 (K=1024) =====
        {
            float d[4] = {0.f, 0.f, 0.f, 0.f};
            run_phase(g_h0f[par][0], g_h0f[par][1], wf0, mi, lane, d);
            ds[r0 * 33 + cc0]           = d[0];
            ds[r0 * 33 + cc0 + 1]       = d[1];
            ds[(r0 + 8) * 33 + cc0]     = d[2];
            ds[(r0 + 8) * 33 + cc0 + 1] = d[3];
        }
        __syncthreads();
        if (tid < 64) {
            const int b = tid;
            const float* gp = g_G0 + ((size_t)t * BATCH + b) * GATES + u_start;
            float hf[8];
#pragma unroll
            for (int u = 0; u < 8; u++) {
                float gi = ds[b * 33 + u * 4 + 0] + gp[u];
                float gf = ds[b * 33 + u * 4 + 1] + gp[HID + u];
                float gg = ds[b * 33 + u * 4 + 2] + gp[2 * HID + u];
                float go = ds[b * 33 + u * 4 + 3] + gp[3 * HID + u];
                float c = sigmoidf_(gf) * c0r[u] + sigmoidf_(gi) * tanhf(gg);
                c0r[u] = c;
                hf[u] = sigmoidf_(go) * tanhf(c);
            }
            store_hfrag(g_h0f[nxt][0], g_h0f[nxt][1], hf, b, cta);
            if (t == T_STEPS - 1) {
                float* so = out + (size_t)T_STEPS * BATCH * HID;
#pragma unroll
                for (int u = 0; u < 8; u++) {
                    so[b * HID + u_start + u]         = hf[u];
                    so[65536 + b * HID + u_start + u] = c0r[u];
                }
            }
        }
        grid_sync(my_epoch);

        // ===== phase 2: layer 1 (K=2048) =====
        {
            float d[4] = {0.f, 0.f, 0.f, 0.f};
            run_phase(g_h0f[nxt][0], g_h0f[nxt][1], wf1, mi, lane, d);
            run_phase(g_h1f[par][0], g_h1f[par][1], wf2, mi, lane, d);
            ds[r0 * 33 + cc0]           = d[0];
            ds[r0 * 33 + cc0 + 1]       = d[1];
            ds[(r0 + 8) * 33 + cc0]     = d[2];
            ds[(r0 + 8) * 33 + cc0 + 1] = d[3];
        }
        __syncthreads();
        if (tid < 64) {
            const int b = tid;
            float hf[8];
#pragma unroll
            for (int u = 0; u < 8; u++) {
                float gi = ds[b * 33 + u * 4 + 0] + b1r[u];
                float gf = ds[b * 33 + u * 4 + 1] + b1r[8 + u];
                float gg = ds[b * 33 + u * 4 + 2] + b1r[16 + u];
                float go = ds[b * 33 + u * 4 + 3] + b1r[24 + u];
                float c = sigmoidf_(gf) * c1r[u] + sigmoidf_(gi) * tanhf(gg);
                c1r[u] = c;
                hf[u] = sigmoidf_(go) * tanhf(c);
            }
            store_hfrag(g_h1f[nxt][0], g_h1f[nxt][1], hf, b, cta);
            float* orow = out + ((size_t)t * BATCH + b) * HID + u_start;
#pragma unroll
            for (int u = 0; u < 8; u++) orow[u] = hf[u];
            if (t == T_STEPS - 1) {
                float* so = out + (size_t)T_STEPS * BATCH * HID;
#pragma unroll
                for (int u = 0; u < 8; u++) {
                    so[131072 + b * HID + u_start + u] = hf[u];
                    so[196608 + b * HID + u_start + u] = c1r[u];
                }
            }
        }
        grid_sync(my_epoch);
    }

    // ---- reset barrier vars for deterministic graph replay ----
    __threadfence();
    __syncthreads();
    if (tid == 0) {
        if (atomicAdd(&g_done_cnt, 1u) == (unsigned)NB - 1u) {
            g_done_cnt = 0u;
            g_bar_cnt  = 0u;
            __threadfence();
            g_bar_epoch = 0u;
        }
    }
}

// ---------------- launch ------------------------------------------------------
extern "C" void kernel_launch(void* const* d_in, const int* in_sizes, int n_in,
                              void* d_out, int out_size) {
    const float* X     = (const float*)d_in[0];
    const float* Wih0  = (const float*)d_in[1];
    const float* Whh0  = (const float*)d_in[2];
    const float* bih0  = (const float*)d_in[3];
    const float* bhh0  = (const float*)d_in[4];
    const float* Wih1  = (const float*)d_in[5];
    const float* Whh1  = (const float*)d_in[6];
    const float* bih1  = (const float*)d_in[7];
    const float* bhh1  = (const float*)d_in[8];
    float* out = (float*)d_out;

    prep_w<<<12288, 256>>>(Whh0, Wih1, Whh1);

    dim3 ggrid(GATES / 64, (T_STEPS * BATCH) / 64);
    gemm_g0<<<ggrid, 256>>>(X, Wih0, bih0, bhh0);

    lstm_persistent<<<NB, NTH>>>(bih1, bhh1, out);
}

// round 9
// speedup vs baseline: 4.8894x; 1.3463x over previous
#include <cuda_runtime.h>
#include <cuda_bf16.h>
#include <cstdint>

typedef unsigned long long ull;
typedef unsigned int uint;

#define T_STEPS 512
#define BATCH   64
#define DIN     512
#define HID     1024
#define GATES   4096
#define NB      128          // persistent grid: 128 CTAs x 8 units = 1024
#define NTH     512          // 16 warps: mi = w&3 (16-row), ni = w>>2 (8-col)
#define UPC     8

// ---------------- scratch -----------------------------------------------------
__device__ float g_G0[(size_t)T_STEPS * BATCH * GATES];       // X@Wih0^T + biases
// weights in per-lane B-fragment order: [cta][mat 3][ni 4][kstep 64][lane 32]
// each entry uint4 = {b0h, b1h, b0l, b1l}
__device__ uint4 g_wf[(size_t)NB * 3 * 4 * 64 * 32];
// hidden states in A-fragment order: [parity][hi/lo][((mt*64+ks)*32+lane)*4+reg]
__device__ uint g_h0f[2][2][32768];
__device__ uint g_h1f[2][2][32768];
__device__ unsigned g_bar_cnt;
__device__ volatile unsigned g_bar_epoch;
__device__ unsigned g_done_cnt;

// ---------------- helpers -----------------------------------------------------
__device__ __forceinline__ void ffma2(ull &acc, ull a, ull b) {
    asm("fma.rn.f32x2 %0, %1, %2, %0;" : "+l"(acc) : "l"(a), "l"(b));
}
__device__ __forceinline__ float f2sum(ull v) {
    union { ull u; float2 f; } x; x.u = v; return x.f.x + x.f.y;
}
__device__ __forceinline__ float sigmoidf_(float x) { return 1.0f / (1.0f + expf(-x)); }

__device__ __forceinline__ void mma16816(float d[4], uint a0, uint a1, uint a2, uint a3,
                                         uint b0, uint b1) {
    asm volatile("mma.sync.aligned.m16n8k16.row.col.f32.bf16.bf16.f32 "
        "{%0,%1,%2,%3}, {%4,%5,%6,%7}, {%8,%9}, {%0,%1,%2,%3};"
        : "+f"(d[0]), "+f"(d[1]), "+f"(d[2]), "+f"(d[3])
        : "r"(a0), "r"(a1), "r"(a2), "r"(a3), "r"(b0), "r"(b1));
}

__device__ __forceinline__ void prefetchL2(const void* p) {
    asm volatile("prefetch.global.L2 [%0];" :: "l"(p));
}

__device__ __forceinline__ void grid_sync(unsigned &my_epoch) {
    __threadfence();
    __syncthreads();
    if (threadIdx.x == 0) {
        my_epoch++;
        if (atomicAdd(&g_bar_cnt, 1u) == (unsigned)NB - 1u) {
            g_bar_cnt = 0u;
            __threadfence();
            g_bar_epoch = my_epoch;
        } else {
            while (g_bar_epoch < my_epoch) { }
            __threadfence();
        }
    }
    __syncthreads();
}

__device__ __forceinline__ uint pack_bf2(__nv_bfloat16 lo16, __nv_bfloat16 hi16) {
    return (uint)__bfloat16_as_ushort(lo16) | ((uint)__bfloat16_as_ushort(hi16) << 16);
}

// ---------------- prep: weights -> B-fragment order, bf16 hi/lo ---------------
// idx = (((cta*3+mat)*4+ni)*64 + ks)*32 + lane
__global__ void __launch_bounds__(256) prep_w(
    const float* __restrict__ Whh0, const float* __restrict__ Wih1,
    const float* __restrict__ Whh1)
{
    uint idx = blockIdx.x * 256u + threadIdx.x;
    uint lane = idx & 31u;
    uint ks   = (idx >> 5) & 63u;
    uint ni   = (idx >> 11) & 3u;
    uint cm   = idx >> 13;
    uint mat  = cm % 3u, cta = cm / 3u;

    const float* W = (mat == 0) ? Whh0 : (mat == 1) ? Wih1 : Whh1;
    uint n  = ni * 8u + (lane >> 2);       // col within CTA's 32: n = lu*4 + g
    uint lu = n >> 2, g = n & 3u;
    const float* row = W + (size_t)(g * HID + cta * UPC + lu) * HID;
    uint k0 = ks * 16u + (lane & 3u) * 2u;

    float f0 = row[k0],     f1 = row[k0 + 1];
    float f2 = row[k0 + 8], f3 = row[k0 + 9];
    __nv_bfloat16 h0 = __float2bfloat16(f0), h1 = __float2bfloat16(f1);
    __nv_bfloat16 h2 = __float2bfloat16(f2), h3 = __float2bfloat16(f3);
    uint4 v;
    v.x = pack_bf2(h0, h1);
    v.y = pack_bf2(h2, h3);
    v.z = pack_bf2(__float2bfloat16(f0 - __bfloat162float(h0)),
                   __float2bfloat16(f1 - __bfloat162float(h1)));
    v.w = pack_bf2(__float2bfloat16(f2 - __bfloat162float(h2)),
                   __float2bfloat16(f3 - __bfloat162float(h3)));
    g_wf[idx] = v;
}

// ---------------- precompute G0 = X @ Wih0^T + b (unchanged, proven) ----------
__global__ void __launch_bounds__(256) gemm_g0(
    const float* __restrict__ X, const float* __restrict__ W,
    const float* __restrict__ bi, const float* __restrict__ bh)
{
    __shared__ ull As[64 * 16];
    __shared__ ull Bs[64 * 16];
    const int tid = threadIdx.x;
    const int tx = tid & 15, ty = tid >> 4;
    const int m0 = blockIdx.y * 64, n0 = blockIdx.x * 64;

    ull acc[4][4];
#pragma unroll
    for (int i = 0; i < 4; i++)
#pragma unroll
        for (int j = 0; j < 4; j++) acc[i][j] = 0ull;

    for (int kb = 0; kb < DIN; kb += 32) {
#pragma unroll
        for (int r = 0; r < 2; r++) {
            int idx = tid + 256 * r;
            int row = idx >> 3, c4 = idx & 7;
            int kk = c4 * 2, s = row & 15;
            ulonglong2 xa = *(const ulonglong2*)&X[(size_t)(m0 + row) * DIN + kb + c4 * 4];
            As[row * 16 + (kk ^ s)]       = xa.x;
            As[row * 16 + ((kk + 1) ^ s)] = xa.y;
            ulonglong2 wb = *(const ulonglong2*)&W[(size_t)(n0 + row) * DIN + kb + c4 * 4];
            Bs[row * 16 + (kk ^ s)]       = wb.x;
            Bs[row * 16 + ((kk + 1) ^ s)] = wb.y;
        }
        __syncthreads();
#pragma unroll
        for (int kk = 0; kk < 16; kk++) {
            ull a[4], b[4];
#pragma unroll
            for (int i = 0; i < 4; i++) { int row = ty * 4 + i; a[i] = As[row * 16 + (kk ^ (row & 15))]; }
#pragma unroll
            for (int j = 0; j < 4; j++) { int row = tx * 4 + j; b[j] = Bs[row * 16 + (kk ^ (row & 15))]; }
#pragma unroll
            for (int i = 0; i < 4; i++)
#pragma unroll
                for (int j = 0; j < 4; j++) ffma2(acc[i][j], a[i], b[j]);
        }
        __syncthreads();
    }

    float bias[4];
#pragma unroll
    for (int j = 0; j < 4; j++) bias[j] = bi[n0 + tx * 4 + j] + bh[n0 + tx * 4 + j];
#pragma unroll
    for (int i = 0; i < 4; i++) {
        float4 v;
        v.x = f2sum(acc[i][0]) + bias[0];
        v.y = f2sum(acc[i][1]) + bias[1];
        v.z = f2sum(acc[i][2]) + bias[2];
        v.w = f2sum(acc[i][3]) + bias[3];
        *(float4*)&g_G0[(size_t)(m0 + ty * 4 + i) * GATES + n0 + tx * 4] = v;
    }
}

// ---------------- k-loop: 3 independent accumulator chains, k-rotated ---------
__device__ __forceinline__ void run_phase3(
    const uint* __restrict__ ah_base, const uint* __restrict__ al_base,
    const uint4* __restrict__ bf_base, int mi, int lane, int rot,
    float dhh[4], float dlh[4], float dhl[4])
{
    const uint4* ah = (const uint4*)ah_base + (size_t)mi * 64 * 32 + lane;
    const uint4* al = (const uint4*)al_base + (size_t)mi * 64 * 32 + lane;
    const uint4* bf = bf_base + lane;
#pragma unroll 4
    for (int i = 0; i < 64; i++) {
        int ks = (i + rot) & 63;
        uint4 a_h = ah[ks * 32];
        uint4 a_l = al[ks * 32];
        uint4 bv  = __ldg(&bf[ks * 32]);
        mma16816(dhh, a_h.x, a_h.y, a_h.z, a_h.w, bv.x, bv.y);   // hi*hi
        mma16816(dlh, a_l.x, a_l.y, a_l.z, a_l.w, bv.x, bv.y);   // lo*hi
        mma16816(dhl, a_h.x, a_h.y, a_h.z, a_h.w, bv.z, bv.w);   // hi*lo
    }
}

// epilogue helper: split h to bf16 hi/lo and write A-fragment slots
__device__ __forceinline__ void store_hfrag(uint* dst_hi, uint* dst_lo,
                                            const float hf[8], int b, int cta) {
    int kstep = cta >> 1, khalf = cta & 1;
    int row = b & 15, mt = b >> 4;
    int regb = ((row >= 8) ? 1 : 0) + (khalf ? 2 : 0);
    int base = (mt * 64 + kstep) * 32 + (row & 7) * 4;
#pragma unroll
    for (int s = 0; s < 4; s++) {
        float x = hf[2 * s], y = hf[2 * s + 1];
        __nv_bfloat16 xh = __float2bfloat16(x), yh = __float2bfloat16(y);
        int idx = (base + s) * 4 + regb;
        dst_hi[idx] = pack_bf2(xh, yh);
        dst_lo[idx] = pack_bf2(__float2bfloat16(x - __bfloat162float(xh)),
                               __float2bfloat16(y - __bfloat162float(yh)));
    }
}

// ---------------- persistent recurrent kernel ---------------------------------
__global__ void __launch_bounds__(NTH) lstm_persistent(
    const float* __restrict__ bi1, const float* __restrict__ bh1,
    float* __restrict__ out)
{
    __shared__ float ds[64 * 33];          // D routing tile, pad 33 -> conflict-free

    const int tid  = threadIdx.x;
    const int lane = tid & 31;
    const int warp = tid >> 5;
    const int mi   = warp & 3;             // 16-row tile
    const int ni   = warp >> 2;            // 8-col tile
    const int cta  = blockIdx.x;
    const int u_start = cta * UPC;
    const int rot  = cta & 63;             // per-CTA k-rotation: de-camp L2 slices

    // zero parity-0 h fragments (first 65536 u32 of each array = parity 0 hi+lo)
    {
        int i0 = cta * NTH + tid;          // 0..65535
        ((uint*)g_h0f)[i0] = 0u;
        ((uint*)g_h1f)[i0] = 0u;
    }
    float c0r[8], c1r[8];
#pragma unroll
    for (int u = 0; u < 8; u++) { c0r[u] = 0.f; c1r[u] = 0.f; }
    float b1r[32];
    if (tid < 64) {
#pragma unroll
        for (int g = 0; g < 4; g++)
#pragma unroll
            for (int u = 0; u < 8; u++)
                b1r[g * 8 + u] = bi1[g * HID + u_start + u] + bh1[g * HID + u_start + u];
    }

    unsigned my_epoch = 0;
    grid_sync(my_epoch);

    const uint4* wf0 = g_wf + ((size_t)(cta * 3 + 0) * 4 + ni) * 2048;
    const uint4* wf1 = g_wf + ((size_t)(cta * 3 + 1) * 4 + ni) * 2048;
    const uint4* wf2 = g_wf + ((size_t)(cta * 3 + 2) * 4 + ni) * 2048;

    const int r0  = 16 * mi + (lane >> 2);
    const int cc0 = 8 * ni + (lane & 3) * 2;

    for (int t = 0; t < T_STEPS; t++) {
        const int par = t & 1, nxt = par ^ 1;

        // L2-prefetch this step's G0 slice (consumed ~20us later in epilogue 1)
        if (tid < 64) {
            const float* gp = g_G0 + ((size_t)t * BATCH + tid) * GATES + u_start;
            prefetchL2(gp);
            prefetchL2(gp + HID);
            prefetchL2(gp + 2 * HID);
            prefetchL2(gp + 3 * HID);
        }

        // ===== phase A: h1_prev@Whh1 (layer-1 partial, barrier-independent)
        //                + h0_prev@Whh0 (layer 0) =====
        float d1hh[4] = {0.f,0.f,0.f,0.f}, d1lh[4] = {0.f,0.f,0.f,0.f}, d1hl[4] = {0.f,0.f,0.f,0.f};
        run_phase3(g_h1f[par][0], g_h1f[par][1], wf2, mi, lane, rot, d1hh, d1lh, d1hl);
        {
            float dhh[4] = {0.f,0.f,0.f,0.f}, dlh[4] = {0.f,0.f,0.f,0.f}, dhl[4] = {0.f,0.f,0.f,0.f};
            run_phase3(g_h0f[par][0], g_h0f[par][1], wf0, mi, lane, rot, dhh, dlh, dhl);
            ds[r0 * 33 + cc0]           = dhh[0] + dlh[0] + dhl[0];
            ds[r0 * 33 + cc0 + 1]       = dhh[1] + dlh[1] + dhl[1];
            ds[(r0 + 8) * 33 + cc0]     = dhh[2] + dlh[2] + dhl[2];
            ds[(r0 + 8) * 33 + cc0 + 1] = dhh[3] + dlh[3] + dhl[3];
        }
        __syncthreads();
        if (tid < 64) {
            const int b = tid;
            const float* gp = g_G0 + ((size_t)t * BATCH + b) * GATES + u_start;
            float hf[8];
#pragma unroll
            for (int u = 0; u < 8; u++) {
                float gi = ds[b * 33 + u * 4 + 0] + gp[u];
                float gf = ds[b * 33 + u * 4 + 1] + gp[HID + u];
                float gg = ds[b * 33 + u * 4 + 2] + gp[2 * HID + u];
                float go = ds[b * 33 + u * 4 + 3] + gp[3 * HID + u];
                float c = sigmoidf_(gf) * c0r[u] + sigmoidf_(gi) * tanhf(gg);
                c0r[u] = c;
                hf[u] = sigmoidf_(go) * tanhf(c);
            }
            store_hfrag(g_h0f[nxt][0], g_h0f[nxt][1], hf, b, cta);
            if (t == T_STEPS - 1) {
                float* so = out + (size_t)T_STEPS * BATCH * HID;
#pragma unroll
                for (int u = 0; u < 8; u++) {
                    so[b * HID + u_start + u]         = hf[u];
                    so[65536 + b * HID + u_start + u] = c0r[u];
                }
            }
        }
        grid_sync(my_epoch);

        // ===== phase B: += h0_new@Wih1 (layer-1 remainder) =====
        run_phase3(g_h0f[nxt][0], g_h0f[nxt][1], wf1, mi, lane, rot, d1hh, d1lh, d1hl);
        ds[r0 * 33 + cc0]           = d1hh[0] + d1lh[0] + d1hl[0];
        ds[r0 * 33 + cc0 + 1]       = d1hh[1] + d1lh[1] + d1hl[1];
        ds[(r0 + 8) * 33 + cc0]     = d1hh[2] + d1lh[2] + d1hl[2];
        ds[(r0 + 8) * 33 + cc0 + 1] = d1hh[3] + d1lh[3] + d1hl[3];
        __syncthreads();
        if (tid < 64) {
            const int b = tid;
            float hf[8];
#pragma unroll
            for (int u = 0; u < 8; u++) {
                float gi = ds[b * 33 + u * 4 + 0] + b1r[u];
                float gf = ds[b * 33 + u * 4 + 1] + b1r[8 + u];
                float gg = ds[b * 33 + u * 4 + 2] + b1r[16 + u];
                float go = ds[b * 33 + u * 4 + 3] + b1r[24 + u];
                float c = sigmoidf_(gf) * c1r[u] + sigmoidf_(gi) * tanhf(gg);
                c1r[u] = c;
                hf[u] = sigmoidf_(go) * tanhf(c);
            }
            store_hfrag(g_h1f[nxt][0], g_h1f[nxt][1], hf, b, cta);
            float* orow = out + ((size_t)t * BATCH + b) * HID + u_start;
            *(float4*)&orow[0] = make_float4(hf[0], hf[1], hf[2], hf[3]);
            *(float4*)&orow[4] = make_float4(hf[4], hf[5], hf[6], hf[7]);
            if (t == T_STEPS - 1) {
                float* so = out + (size_t)T_STEPS * BATCH * HID;
#pragma unroll
                for (int u = 0; u < 8; u++) {
                    so[131072 + b * HID + u_start + u] = hf[u];
                    so[196608 + b * HID + u_start + u] = c1r[u];
                }
            }
        }
        grid_sync(my_epoch);
    }

    // ---- reset barrier vars for deterministic graph replay ----
    __threadfence();
    __syncthreads();
    if (tid == 0) {
        if (atomicAdd(&g_done_cnt, 1u) == (unsigned)NB - 1u) {
            g_done_cnt = 0u;
            g_bar_cnt  = 0u;
            __threadfence();
            g_bar_epoch = 0u;
        }
    }
}

// ---------------- launch ------------------------------------------------------
extern "C" void kernel_launch(void* const* d_in, const int* in_sizes, int n_in,
                              void* d_out, int out_size) {
    const float* X     = (const float*)d_in[0];
    const float* Wih0  = (const float*)d_in[1];
    const float* Whh0  = (const float*)d_in[2];
    const float* bih0  = (const float*)d_in[3];
    const float* bhh0  = (const float*)d_in[4];
    const float* Wih1  = (const float*)d_in[5];
    const float* Whh1  = (const float*)d_in[6];
    const float* bih1  = (const float*)d_in[7];
    const float* bhh1  = (const float*)d_in[8];
    float* out = (float*)d_out;

    prep_w<<<12288, 256>>>(Whh0, Wih1, Whh1);

    dim3 ggrid(GATES / 64, (T_STEPS * BATCH) / 64);
    gemm_g0<<<ggrid, 256>>>(X, Wih0, bih0, bhh0);

    lstm_persistent<<<NB, NTH>>>(bih1, bhh1, out);
}